// round 14
// baseline (speedup 1.0000x reference)
#include <cuda_runtime.h>
#include <cuda_bf16.h>
#include <cstdint>

// Problem constants (fixed-shape dataset)
#define NN 100000   // nodes
#define NE 600000   // edges
#define DD 128      // embed dim
#define NG 1000     // graphs
#define NL 3        // gcn layers

#define SCAN_BLK 256
#define NBLK ((NN + SCAN_BLK - 1) / SCAN_BLK)   // 391

#define GEMM_TILES ((NN + 127) / 128)           // 782

// padded smem strides (bf16 elements)
#define TP 136                                   // B tile row stride
#define TPA 72                                   // A chunk row stride (64 + 8 pad)
#define TILE_USH (128 * TP)                      // 17408 ushorts per B tile
#define ACH_USH (128 * TPA)                      // 9216 ushorts per A chunk
#define SMEMSZ ((2 * TILE_USH + 2 * ACH_USH) * 2)  // 106496 B -> 2 CTAs/SM

// lookback status flags
#define LB_A (1u << 29)
#define LB_P (1u << 30)
#define LB_MASK ((1u << 29) - 1u)

// Scratch (device globals: allocation-free per harness rules)
__device__ float g_bufA[(size_t)NN * DD];   // aggregated layer output
__device__ float g_bufB[(size_t)NN * DD];   // transform output (h @ W)
__device__ float g_dinv[NN];                // rsqrt(deg+1)
__device__ float g_s[NN];                   // per-node score
__device__ int   g_counts[NN];              // in-degree histogram
__device__ int   g_rank[NE];                // per-edge arrival rank within dst
__device__ int   g_offs[NN + 1];            // CSR offsets
__device__ int   g_stat[NBLK];              // lookback status
__device__ int2  g_sorted[NE];              // (src, bitcast(edge_norm)) grouped by dst
// weight tiles, transposed [n][k] row-major bf16 hi/lo: [4 matrices][16384]
__device__ unsigned short g_wbhi[4 * 16384];
__device__ unsigned short g_wblo[4 * 16384];

__device__ __forceinline__ uint32_t smem_u32(const void* p) {
    uint32_t a;
    asm("{ .reg .u64 t; cvta.to.shared.u64 t, %1; cvt.u32.u64 %0, t; }" : "=r"(a) : "l"(p));
    return a;
}

__device__ __forceinline__ void ldsm_x4(uint32_t* r, uint32_t addr) {
    asm volatile("ldmatrix.sync.aligned.m8n8.x4.shared.b16 {%0,%1,%2,%3}, [%4];"
                 : "=r"(r[0]), "=r"(r[1]), "=r"(r[2]), "=r"(r[3]) : "r"(addr));
}

__device__ __forceinline__ void mma_bf16(float* d, const uint32_t* a,
                                         uint32_t b0, uint32_t b1) {
    asm volatile(
        "mma.sync.aligned.m16n8k16.row.col.f32.bf16.bf16.f32 "
        "{%0,%1,%2,%3}, {%4,%5,%6,%7}, {%8,%9}, {%0,%1,%2,%3};"
        : "+f"(d[0]), "+f"(d[1]), "+f"(d[2]), "+f"(d[3])
        : "r"(a[0]), "r"(a[1]), "r"(a[2]), "r"(a[3]), "r"(b0), "r"(b1));
}

// fp32 pair -> packed bf16x2 hi + lo (split-2)
__device__ __forceinline__ void split2_pair(float x, float y,
                                            uint32_t& hi, uint32_t& lo) {
    __nv_bfloat162 h = __float22bfloat162_rn(make_float2(x, y));
    uint32_t hb = *reinterpret_cast<uint32_t*>(&h);
    float hf0 = __uint_as_float(hb << 16);
    float hf1 = __uint_as_float(hb & 0xffff0000u);
    __nv_bfloat162 l = __float22bfloat162_rn(make_float2(x - hf0, y - hf1));
    hi = hb;
    lo = *reinterpret_cast<uint32_t*>(&l);
}

// ---------------------------------------------------------------------------
// CSR build: zero -> histogram(+rank stash) -> lookback scan -> atomic-free place
// ---------------------------------------------------------------------------
__global__ void k_zero2(int* counts, int* stat) {
    int i = blockIdx.x * blockDim.x + threadIdx.x;
    if (i < NN) counts[i] = 0;
    if (i < NBLK) stat[i] = 0;
}

__global__ void k_hist_rank(const int* __restrict__ dst, int* __restrict__ counts,
                            int* __restrict__ rank) {
    int e = blockIdx.x * blockDim.x + threadIdx.x;
    if (e < NE) rank[e] = atomicAdd(&counts[dst[e]], 1);
}

__global__ __launch_bounds__(SCAN_BLK) void k_scan_lb(const int* __restrict__ counts,
                                                      int* __restrict__ stat,
                                                      int* __restrict__ offs,
                                                      float* __restrict__ dinv)
{
    __shared__ int wsum[8];
    __shared__ int s_prefix;
    const int tid = threadIdx.x;
    const int lane = tid & 31;
    const int wid = tid >> 5;
    const int bid = blockIdx.x;
    int i = bid * SCAN_BLK + tid;

    int v = (i < NN) ? counts[i] : 0;
    if (i < NN) dinv[i] = rsqrtf((float)v + 1.0f);

    int x = v;
#pragma unroll
    for (int o = 1; o < 32; o <<= 1) {
        int y = __shfl_up_sync(0xffffffffu, x, o);
        if (lane >= o) x += y;
    }
    if (lane == 31) wsum[wid] = x;
    __syncthreads();
    if (wid == 0) {
        int s = (lane < 8) ? wsum[lane] : 0;
#pragma unroll
        for (int o = 1; o < 8; o <<= 1) {
            int y = __shfl_up_sync(0xffffffffu, s, o);
            if (lane >= o) s += y;
        }
        if (lane < 8) wsum[lane] = s;
    }
    __syncthreads();
    int incl = x + ((wid > 0) ? wsum[wid - 1] : 0);
    int total = wsum[7];

    if (tid == 0) {
        int prefix = 0;
        if (bid == 0) {
            atomicExch(&stat[0], (int)(LB_P | (uint32_t)total));
        } else {
            atomicExch(&stat[bid], (int)(LB_A | (uint32_t)total));
            int j = bid - 1;
            for (;;) {
                int s;
                do { s = atomicAdd(&stat[j], 0); } while (s == 0);
                prefix += (int)((uint32_t)s & LB_MASK);
                if ((uint32_t)s & LB_P) break;
                j--;
            }
            atomicExch(&stat[bid], (int)(LB_P | (uint32_t)(prefix + total)));
        }
        s_prefix = prefix;
    }
    __syncthreads();

    int excl = s_prefix + incl - v;
    if (i < NN) offs[i] = excl;
    if (i == NN - 1) offs[NN] = excl + v;
}

__global__ void k_place_rank(const int* __restrict__ src, const int* __restrict__ dst,
                             const int* __restrict__ rank, const int* __restrict__ offs,
                             const float* __restrict__ dinv, int2* __restrict__ sorted)
{
    int e = blockIdx.x * blockDim.x + threadIdx.x;
    if (e >= NE) return;
    int s = src[e];
    int d = dst[e];
    float en = dinv[s] * dinv[d];
    sorted[offs[d] + rank[e]] = make_int2(s, __float_as_int(en));
}

// ---------------------------------------------------------------------------
// weight prep: W[128x128] fp32 -> transposed B[n][k] bf16 hi/lo, row-major.
// ---------------------------------------------------------------------------
__global__ __launch_bounds__(256) void k_prepw(const float* __restrict__ gcn_w,
                                               const float* __restrict__ lin1_w,
                                               unsigned short* __restrict__ whi,
                                               unsigned short* __restrict__ wlo)
{
    int m = blockIdx.x;                       // 0..3
    const float* W = (m < 3) ? gcn_w + (size_t)m * 16384 : lin1_w;
    unsigned short* oh = whi + (size_t)m * 16384;
    unsigned short* ol = wlo + (size_t)m * 16384;
    for (int idx = threadIdx.x; idx < 16384; idx += 256) {
        int nrow = idx >> 7;
        int k = idx & 127;
        float v = W[(size_t)k * 128 + nrow];
        __nv_bfloat16 h = __float2bfloat16(v);
        __nv_bfloat16 l = __float2bfloat16(v - __bfloat162float(h));
        oh[idx] = __bfloat16_as_ushort(h);
        ol[idx] = __bfloat16_as_ushort(l);
    }
}

// ---------------------------------------------------------------------------
// mma.sync bf16 split-2 GEMM: C[n x 128] = A[n x 128] @ W   (fp32-grade)
// CTA: 128 rows, 8 warps; warp: M=16, N=128. 3 passes: hh + hl + lh.
// A staged via smem in two 64-col chunks -> 104KB smem -> 2 CTAs/SM.
// do_head: fused MLP head epilogue (relu(.+b1).w2+b2, mask) -> S, no C store.
// ---------------------------------------------------------------------------
__global__ __launch_bounds__(256, 2) void k_gemm_mma(
    const float* __restrict__ A,
    const unsigned short* __restrict__ whi,
    const unsigned short* __restrict__ wlo,
    float* __restrict__ C, int n, int do_head,
    const float* __restrict__ b1, const float* __restrict__ w2,
    const float* __restrict__ b2p, const int* __restrict__ mask,
    float* __restrict__ S)
{
    extern __shared__ __align__(16) unsigned short smem[];
    unsigned short* Bhi = smem;
    unsigned short* Blo = Bhi + TILE_USH;
    unsigned short* Ahi = Blo + TILE_USH;
    unsigned short* Alo = Ahi + ACH_USH;

    const int tid = threadIdx.x;
    const int wid = tid >> 5;
    const int lane = tid & 31;
    const int r0 = blockIdx.x * 128;
    const int wr = wid * 16;

    // ---- load weight tiles into padded smem (full k=128)
    {
        const uint4* sh = (const uint4*)whi;
        const uint4* sl = (const uint4*)wlo;
#pragma unroll
        for (int p = 0; p < 8; p++) {
            int i = p * 256 + tid;
            int row = i >> 4;
            int c8 = i & 15;
            *(uint4*)(Bhi + row * TP + c8 * 8) = sh[i];
            *(uint4*)(Blo + row * TP + c8 * 8) = sl[i];
        }
    }

    // fragment addressing
    uint32_t a_row = (uint32_t)(wr + ((lane >> 3) & 1) * 8 + (lane & 7));
    uint32_t a_colb = (uint32_t)((lane >> 4) * 8) * 2;
    uint32_t ahi_base = smem_u32(Ahi) + a_row * (TPA * 2) + a_colb;
    uint32_t alo_base = smem_u32(Alo) + a_row * (TPA * 2) + a_colb;
    uint32_t b_row = (uint32_t)((lane >> 4) * 8 + (lane & 7));
    uint32_t b_col = (uint32_t)(((lane >> 3) & 1) * 8);
    uint32_t bhi_base = smem_u32(Bhi) + (b_row * TP + b_col) * 2;
    uint32_t blo_base = smem_u32(Blo) + (b_row * TP + b_col) * 2;

    float d[16][4];
#pragma unroll
    for (int i = 0; i < 16; i++)
#pragma unroll
        for (int j = 0; j < 4; j++) d[i][j] = 0.f;

#pragma unroll
    for (int kc = 0; kc < 2; kc++) {
        __syncthreads();   // previous chunk's mma done before overwrite
#pragma unroll
        for (int it = 0; it < 8; it++) {
            int idx = it * 256 + tid;
            int row = idx >> 4;
            int c4 = idx & 15;
            int grow = r0 + row;
            float4 v = make_float4(0.f, 0.f, 0.f, 0.f);
            if (grow < n)
                v = *(const float4*)(A + (size_t)grow * DD + kc * 64 + c4 * 4);

            uint2 hp, lp;
            split2_pair(v.x, v.y, hp.x, lp.x);
            split2_pair(v.z, v.w, hp.y, lp.y);
            *(uint2*)(Ahi + row * TPA + c4 * 4) = hp;
            *(uint2*)(Alo + row * TPA + c4 * 4) = lp;
        }
        __syncthreads();

#pragma unroll
        for (int ks = 0; ks < 4; ks++) {
            uint32_t koff_a = (uint32_t)(ks * 16) * 2;
            uint32_t koff_b = (uint32_t)((kc * 64 + ks * 16) * 2);
            uint32_t ahi[4], alo[4];
            ldsm_x4(ahi, ahi_base + koff_a);
            ldsm_x4(alo, alo_base + koff_a);
#pragma unroll
            for (int nt2 = 0; nt2 < 8; nt2++) {
                uint32_t noff = (uint32_t)(nt2 * 16 * TP) * 2;
                uint32_t bh[4], bl[4];
                ldsm_x4(bh, bhi_base + noff + koff_b);
                ldsm_x4(bl, blo_base + noff + koff_b);
                mma_bf16(d[2 * nt2],     ahi, bh[0], bh[1]);
                mma_bf16(d[2 * nt2],     ahi, bl[0], bl[1]);
                mma_bf16(d[2 * nt2],     alo, bh[0], bh[1]);
                mma_bf16(d[2 * nt2 + 1], ahi, bh[2], bh[3]);
                mma_bf16(d[2 * nt2 + 1], ahi, bl[2], bl[3]);
                mma_bf16(d[2 * nt2 + 1], alo, bh[2], bh[3]);
            }
        }
    }

    // ---- epilogue
    const int g = lane >> 2;
    const int t = lane & 3;
    const int row0 = r0 + wr + g;
    const int row1 = row0 + 8;
    const bool p0 = row0 < n;
    const bool p1 = row1 < n;

    if (!do_head) {
#pragma unroll
        for (int nt = 0; nt < 16; nt++) {
            int col = nt * 8 + t * 2;
            if (p0)
                *(float2*)(C + (size_t)row0 * DD + col) = make_float2(d[nt][0], d[nt][1]);
            if (p1)
                *(float2*)(C + (size_t)row1 * DD + col) = make_float2(d[nt][2], d[nt][3]);
        }
    } else {
        float s0 = 0.f, s1 = 0.f;
#pragma unroll
        for (int nt = 0; nt < 16; nt++) {
            int c = nt * 8 + t * 2;
            float bb0 = b1[c], bb1 = b1[c + 1];
            float w0 = w2[c],  w1 = w2[c + 1];
            s0 += fmaxf(d[nt][0] + bb0, 0.f) * w0 + fmaxf(d[nt][1] + bb1, 0.f) * w1;
            s1 += fmaxf(d[nt][2] + bb0, 0.f) * w0 + fmaxf(d[nt][3] + bb1, 0.f) * w1;
        }
#pragma unroll
        for (int o = 1; o < 4; o <<= 1) {
            s0 += __shfl_xor_sync(0xffffffffu, s0, o);
            s1 += __shfl_xor_sync(0xffffffffu, s1, o);
        }
        if (t == 0) {
            float b2 = b2p[0];
            if (p0) {
                float sv = s0 + b2;
                if (mask[row0] == 0) sv = -1e9f;
                S[row0] = sv;
            }
            if (p1) {
                float sv = s1 + b2;
                if (mask[row1] == 0) sv = -1e9f;
                S[row1] = sv;
            }
        }
    }
}

// ---------------------------------------------------------------------------
// gather-aggregate: one warp per node, 4-wide software-pipelined edge loop
// OUT[i] = relu?( H[i]*dinv[i]^2 + bias + sum_{e in CSR[i]} H[src_e]*en_e )
// ---------------------------------------------------------------------------
__global__ __launch_bounds__(256) void k_aggregate(const float* __restrict__ H,
                                                   const int* __restrict__ offs,
                                                   const int2* __restrict__ sorted,
                                                   const float* __restrict__ dinv,
                                                   const float* __restrict__ bias,
                                                   float* __restrict__ OUT,
                                                   int do_relu)
{
    int g = blockIdx.x * blockDim.x + threadIdx.x;
    int i = g >> 5;
    int lane = g & 31;
    if (i >= NN) return;

    float di = dinv[i];
    float sn = di * di;

    float4 h = *(const float4*)(H + (size_t)i * DD + lane * 4);
    float4 b = *(const float4*)(bias + lane * 4);
    float4 acc = make_float4(fmaf(h.x, sn, b.x), fmaf(h.y, sn, b.y),
                             fmaf(h.z, sn, b.z), fmaf(h.w, sn, b.w));

    int e0 = offs[i];
    int e1 = offs[i + 1];

    int e = e0;
    // 4-wide pipelined main loop: four independent gathers in flight
    for (; e + 3 < e1; e += 4) {
        int2 pa = sorted[e];
        int2 pb = sorted[e + 1];
        int2 pc = sorted[e + 2];
        int2 pd = sorted[e + 3];
        float4 va = *(const float4*)(H + (size_t)pa.x * DD + lane * 4);
        float4 vb = *(const float4*)(H + (size_t)pb.x * DD + lane * 4);
        float4 vc = *(const float4*)(H + (size_t)pc.x * DD + lane * 4);
        float4 vd = *(const float4*)(H + (size_t)pd.x * DD + lane * 4);
        float ea = __int_as_float(pa.y);
        float eb = __int_as_float(pb.y);
        float ec = __int_as_float(pc.y);
        float ed = __int_as_float(pd.y);
        acc.x = fmaf(va.x, ea, acc.x); acc.y = fmaf(va.y, ea, acc.y);
        acc.z = fmaf(va.z, ea, acc.z); acc.w = fmaf(va.w, ea, acc.w);
        acc.x = fmaf(vb.x, eb, acc.x); acc.y = fmaf(vb.y, eb, acc.y);
        acc.z = fmaf(vb.z, eb, acc.z); acc.w = fmaf(vb.w, eb, acc.w);
        acc.x = fmaf(vc.x, ec, acc.x); acc.y = fmaf(vc.y, ec, acc.y);
        acc.z = fmaf(vc.z, ec, acc.z); acc.w = fmaf(vc.w, ec, acc.w);
        acc.x = fmaf(vd.x, ed, acc.x); acc.y = fmaf(vd.y, ed, acc.y);
        acc.z = fmaf(vd.z, ed, acc.z); acc.w = fmaf(vd.w, ed, acc.w);
    }
    for (; e < e1; e++) {
        int2 p = sorted[e];
        float en = __int_as_float(p.y);
        float4 v = *(const float4*)(H + (size_t)p.x * DD + lane * 4);
        acc.x = fmaf(v.x, en, acc.x);
        acc.y = fmaf(v.y, en, acc.y);
        acc.z = fmaf(v.z, en, acc.z);
        acc.w = fmaf(v.w, en, acc.w);
    }

    if (do_relu) {
        acc.x = fmaxf(acc.x, 0.f); acc.y = fmaxf(acc.y, 0.f);
        acc.z = fmaxf(acc.z, 0.f); acc.w = fmaxf(acc.w, 0.f);
    }
    *(float4*)(OUT + (size_t)i * DD + lane * 4) = acc;
}

// ---------------------------------------------------------------------------
// per-graph segment softmax (batch is sorted) — one block per graph
// ---------------------------------------------------------------------------
__device__ __forceinline__ int lower_bound(const int* __restrict__ a, int n, int v) {
    int lo = 0, hi = n;
    while (lo < hi) {
        int mid = (lo + hi) >> 1;
        if (a[mid] < v) lo = mid + 1; else hi = mid;
    }
    return lo;
}

__global__ __launch_bounds__(256) void k_softmax(const float* __restrict__ S,
                                                 const int* __restrict__ batch,
                                                 float* __restrict__ out)
{
    __shared__ float red[256];
    __shared__ int seg[2];
    const int tid = threadIdx.x;
    const int g = blockIdx.x;

    if (tid == 0) {
        seg[0] = lower_bound(batch, NN, g);
        seg[1] = lower_bound(batch, NN, g + 1);
    }
    __syncthreads();
    const int start = seg[0], end = seg[1];
    if (start >= end) return;

    float m = -3.4e38f;
    for (int i = start + tid; i < end; i += 256) m = fmaxf(m, S[i]);
    red[tid] = m;
    __syncthreads();
    for (int o = 128; o > 0; o >>= 1) {
        if (tid < o) red[tid] = fmaxf(red[tid], red[tid + o]);
        __syncthreads();
    }
    m = red[0];
    __syncthreads();

    float z = 0.f;
    for (int i = start + tid; i < end; i += 256) {
        float e = expf(S[i] - m);
        out[i] = e;
        z += e;
    }
    red[tid] = z;
    __syncthreads();
    for (int o = 128; o > 0; o >>= 1) {
        if (tid < o) red[tid] += red[tid + o];
        __syncthreads();
    }
    z = red[0];

    float inv = 1.0f / z;
    for (int i = start + tid; i < end; i += 256) out[i] *= inv;
}

// ---------------------------------------------------------------------------
// launch: CSR chain forked onto a second stream, joined before first aggregate
// ---------------------------------------------------------------------------
extern "C" void kernel_launch(void* const* d_in, const int* in_sizes, int n_in,
                              void* d_out, int out_size)
{
    const float* x       = (const float*)d_in[0];
    const int*   eidx    = (const int*)d_in[1];
    const int*   batch   = (const int*)d_in[2];
    const int*   mask    = (const int*)d_in[3];
    const float* gcn_w   = (const float*)d_in[4];
    const float* gcn_b   = (const float*)d_in[5];
    const float* lin1_w  = (const float*)d_in[6];
    const float* lin1_b  = (const float*)d_in[7];
    const float* lin2_w  = (const float*)d_in[8];
    const float* lin2_b  = (const float*)d_in[9];
    float* out = (float*)d_out;

    const int* src = eidx;
    const int* dst = eidx + NE;

    float *bufA, *bufB, *dinv, *sbuf;
    int *counts, *rank, *offs, *stat;
    int2 *sorted;
    unsigned short *whi, *wlo;
    cudaGetSymbolAddress((void**)&bufA, g_bufA);
    cudaGetSymbolAddress((void**)&bufB, g_bufB);
    cudaGetSymbolAddress((void**)&dinv, g_dinv);
    cudaGetSymbolAddress((void**)&sbuf, g_s);
    cudaGetSymbolAddress((void**)&counts, g_counts);
    cudaGetSymbolAddress((void**)&rank, g_rank);
    cudaGetSymbolAddress((void**)&offs, g_offs);
    cudaGetSymbolAddress((void**)&stat, g_stat);
    cudaGetSymbolAddress((void**)&sorted, g_sorted);
    cudaGetSymbolAddress((void**)&whi, g_wbhi);
    cudaGetSymbolAddress((void**)&wlo, g_wblo);

    cudaFuncSetAttribute(k_gemm_mma, cudaFuncAttributeMaxDynamicSharedMemorySize, SMEMSZ);

    // fork a side stream for the CSR build (capturable fork-join pattern)
    cudaStream_t s2;
    cudaStreamCreateWithFlags(&s2, cudaStreamNonBlocking);
    cudaEvent_t evFork, evCSR;
    cudaEventCreateWithFlags(&evFork, cudaEventDisableTiming);
    cudaEventCreateWithFlags(&evCSR, cudaEventDisableTiming);

    cudaEventRecord(evFork, 0);
    cudaStreamWaitEvent(s2, evFork, 0);

    // CSR build on s2
    k_zero2<<<(NN + 255) / 256, 256, 0, s2>>>(counts, stat);
    k_hist_rank<<<(NE + 255) / 256, 256, 0, s2>>>(dst, counts, rank);
    k_scan_lb<<<NBLK, SCAN_BLK, 0, s2>>>(counts, stat, offs, dinv);
    k_place_rank<<<(NE + 255) / 256, 256, 0, s2>>>(src, dst, rank, offs, dinv, sorted);
    cudaEventRecord(evCSR, s2);

    const int agg_blocks = (NN * 32 + 255) / 256;

    // main stream: weight prep + layer-0 GEMM overlap with the CSR build
    k_prepw<<<4, 256>>>(gcn_w, lin1_w, whi, wlo);
    k_gemm_mma<<<GEMM_TILES, 256, SMEMSZ>>>(x, whi, wlo, bufB, NN, 0,
                                            nullptr, nullptr, nullptr, nullptr, nullptr);

    // join: aggregate needs offs/sorted/dinv
    cudaStreamWaitEvent(0, evCSR, 0);

    const float* in_ptr = nullptr;
    for (int l = 0; l < NL; l++) {
        if (l > 0) {
            k_gemm_mma<<<GEMM_TILES, 256, SMEMSZ>>>(in_ptr,
                                                    whi + (size_t)l * 16384,
                                                    wlo + (size_t)l * 16384,
                                                    bufB, NN, 0,
                                                    nullptr, nullptr, nullptr, nullptr, nullptr);
        }
        k_aggregate<<<agg_blocks, 256>>>(bufB, offs, sorted, dinv,
                                         gcn_b + (size_t)l * DD, bufA,
                                         (l < NL - 1) ? 1 : 0);
        in_ptr = bufA;
    }

    // MLP GEMM with fused head -> per-node score
    k_gemm_mma<<<GEMM_TILES, 256, SMEMSZ>>>(bufA, whi + (size_t)3 * 16384,
                                            wlo + (size_t)3 * 16384,
                                            nullptr, NN, 1,
                                            lin1_b, lin2_w, lin2_b, mask, sbuf);

    // per-graph softmax
    k_softmax<<<NG, 256>>>(sbuf, batch, out);

    cudaEventDestroy(evFork);
    cudaEventDestroy(evCSR);
    cudaStreamDestroy(s2);
}

// round 15
// speedup vs baseline: 1.0410x; 1.0410x over previous
#include <cuda_runtime.h>
#include <cuda_bf16.h>
#include <cstdint>

// Problem constants (fixed-shape dataset)
#define NN 100000   // nodes
#define NE 600000   // edges
#define DD 128      // embed dim
#define NG 1000     // graphs
#define NL 3        // gcn layers

#define SCAN_BLK 256
#define NBLK ((NN + SCAN_BLK - 1) / SCAN_BLK)   // 391

#define GEMM_TILES ((NN + 127) / 128)           // 782

// padded smem strides (bf16 elements)
#define TP 136                                   // B tile row stride
#define TPA 72                                   // A chunk row stride (64 + 8 pad)
#define TILE_USH (128 * TP)                      // 17408 ushorts per B tile
#define ACH_USH (128 * TPA)                      // 9216 ushorts per A chunk
#define SMEMSZ ((2 * TILE_USH + 2 * ACH_USH) * 2)  // 106496 B -> 2 CTAs/SM

// lookback status flags
#define LB_A (1u << 29)
#define LB_P (1u << 30)
#define LB_MASK ((1u << 29) - 1u)

// Scratch (device globals: allocation-free per harness rules)
__device__ float g_bufA[(size_t)NN * DD];   // aggregated layer output
__device__ float g_bufB[(size_t)NN * DD];   // transform output (h @ W)
__device__ float g_dinv[NN];                // rsqrt(deg+1)
__device__ float g_s[NN];                   // per-node score
__device__ int   g_counts[NN];              // in-degree histogram
__device__ int   g_rank[NE];                // per-edge arrival rank within dst
__device__ int   g_offs[NN + 1];            // CSR offsets
__device__ int   g_stat[NBLK];              // lookback status
__device__ int2  g_sorted[NE];              // (src, bitcast(edge_norm)) grouped by dst
// weight tiles, transposed [n][k] row-major bf16 hi/lo: [4 matrices][16384]
__device__ unsigned short g_wbhi[4 * 16384];
__device__ unsigned short g_wblo[4 * 16384];

__device__ __forceinline__ uint32_t smem_u32(const void* p) {
    uint32_t a;
    asm("{ .reg .u64 t; cvta.to.shared.u64 t, %1; cvt.u32.u64 %0, t; }" : "=r"(a) : "l"(p));
    return a;
}

__device__ __forceinline__ void ldsm_x4(uint32_t* r, uint32_t addr) {
    asm volatile("ldmatrix.sync.aligned.m8n8.x4.shared.b16 {%0,%1,%2,%3}, [%4];"
                 : "=r"(r[0]), "=r"(r[1]), "=r"(r[2]), "=r"(r[3]) : "r"(addr));
}

__device__ __forceinline__ void mma_bf16(float* d, const uint32_t* a,
                                         uint32_t b0, uint32_t b1) {
    asm volatile(
        "mma.sync.aligned.m16n8k16.row.col.f32.bf16.bf16.f32 "
        "{%0,%1,%2,%3}, {%4,%5,%6,%7}, {%8,%9}, {%0,%1,%2,%3};"
        : "+f"(d[0]), "+f"(d[1]), "+f"(d[2]), "+f"(d[3])
        : "r"(a[0]), "r"(a[1]), "r"(a[2]), "r"(a[3]), "r"(b0), "r"(b1));
}

// fp32 pair -> packed bf16x2 hi + lo (split-2)
__device__ __forceinline__ void split2_pair(float x, float y,
                                            uint32_t& hi, uint32_t& lo) {
    __nv_bfloat162 h = __float22bfloat162_rn(make_float2(x, y));
    uint32_t hb = *reinterpret_cast<uint32_t*>(&h);
    float hf0 = __uint_as_float(hb << 16);
    float hf1 = __uint_as_float(hb & 0xffff0000u);
    __nv_bfloat162 l = __float22bfloat162_rn(make_float2(x - hf0, y - hf1));
    hi = hb;
    lo = *reinterpret_cast<uint32_t*>(&l);
}

// ---------------------------------------------------------------------------
// CSR build: zero -> histogram(+rank stash) -> lookback scan -> atomic-free place
// ---------------------------------------------------------------------------
__global__ void k_zero2(int* counts, int* stat) {
    int i = blockIdx.x * blockDim.x + threadIdx.x;
    if (i < NN) counts[i] = 0;
    if (i < NBLK) stat[i] = 0;
}

__global__ void k_hist_rank(const int* __restrict__ dst, int* __restrict__ counts,
                            int* __restrict__ rank) {
    int e = blockIdx.x * blockDim.x + threadIdx.x;
    if (e < NE) rank[e] = atomicAdd(&counts[dst[e]], 1);
}

__global__ __launch_bounds__(SCAN_BLK) void k_scan_lb(const int* __restrict__ counts,
                                                      int* __restrict__ stat,
                                                      int* __restrict__ offs,
                                                      float* __restrict__ dinv)
{
    __shared__ int wsum[8];
    __shared__ int s_prefix;
    const int tid = threadIdx.x;
    const int lane = tid & 31;
    const int wid = tid >> 5;
    const int bid = blockIdx.x;
    int i = bid * SCAN_BLK + tid;

    int v = (i < NN) ? counts[i] : 0;
    if (i < NN) dinv[i] = rsqrtf((float)v + 1.0f);

    int x = v;
#pragma unroll
    for (int o = 1; o < 32; o <<= 1) {
        int y = __shfl_up_sync(0xffffffffu, x, o);
        if (lane >= o) x += y;
    }
    if (lane == 31) wsum[wid] = x;
    __syncthreads();
    if (wid == 0) {
        int s = (lane < 8) ? wsum[lane] : 0;
#pragma unroll
        for (int o = 1; o < 8; o <<= 1) {
            int y = __shfl_up_sync(0xffffffffu, s, o);
            if (lane >= o) s += y;
        }
        if (lane < 8) wsum[lane] = s;
    }
    __syncthreads();
    int incl = x + ((wid > 0) ? wsum[wid - 1] : 0);
    int total = wsum[7];

    if (tid == 0) {
        int prefix = 0;
        if (bid == 0) {
            atomicExch(&stat[0], (int)(LB_P | (uint32_t)total));
        } else {
            atomicExch(&stat[bid], (int)(LB_A | (uint32_t)total));
            int j = bid - 1;
            for (;;) {
                int s;
                do { s = atomicAdd(&stat[j], 0); } while (s == 0);
                prefix += (int)((uint32_t)s & LB_MASK);
                if ((uint32_t)s & LB_P) break;
                j--;
            }
            atomicExch(&stat[bid], (int)(LB_P | (uint32_t)(prefix + total)));
        }
        s_prefix = prefix;
    }
    __syncthreads();

    int excl = s_prefix + incl - v;
    if (i < NN) offs[i] = excl;
    if (i == NN - 1) offs[NN] = excl + v;
}

__global__ void k_place_rank(const int* __restrict__ src, const int* __restrict__ dst,
                             const int* __restrict__ rank, const int* __restrict__ offs,
                             const float* __restrict__ dinv, int2* __restrict__ sorted)
{
    int e = blockIdx.x * blockDim.x + threadIdx.x;
    if (e >= NE) return;
    int s = src[e];
    int d = dst[e];
    float en = dinv[s] * dinv[d];
    sorted[offs[d] + rank[e]] = make_int2(s, __float_as_int(en));
}

// ---------------------------------------------------------------------------
// weight prep: W[128x128] fp32 -> transposed B[n][k] bf16 hi/lo, row-major.
// ---------------------------------------------------------------------------
__global__ __launch_bounds__(256) void k_prepw(const float* __restrict__ gcn_w,
                                               const float* __restrict__ lin1_w,
                                               unsigned short* __restrict__ whi,
                                               unsigned short* __restrict__ wlo)
{
    int m = blockIdx.x;                       // 0..3
    const float* W = (m < 3) ? gcn_w + (size_t)m * 16384 : lin1_w;
    unsigned short* oh = whi + (size_t)m * 16384;
    unsigned short* ol = wlo + (size_t)m * 16384;
    for (int idx = threadIdx.x; idx < 16384; idx += 256) {
        int nrow = idx >> 7;
        int k = idx & 127;
        float v = W[(size_t)k * 128 + nrow];
        __nv_bfloat16 h = __float2bfloat16(v);
        __nv_bfloat16 l = __float2bfloat16(v - __bfloat162float(h));
        oh[idx] = __bfloat16_as_ushort(h);
        ol[idx] = __bfloat16_as_ushort(l);
    }
}

// ---------------------------------------------------------------------------
// mma.sync bf16 split-2 GEMM: C[n x 128] = A[n x 128] @ W   (fp32-grade)
// CTA: 128 rows, 8 warps; warp: M=16, N=128. 3 passes: hh + hl + lh.
// A staged via smem in two 64-col chunks -> 104KB smem -> 2 CTAs/SM.
// do_head: fused MLP head epilogue (relu(.+b1).w2+b2, mask) -> S, no C store.
// ---------------------------------------------------------------------------
__global__ __launch_bounds__(256, 2) void k_gemm_mma(
    const float* __restrict__ A,
    const unsigned short* __restrict__ whi,
    const unsigned short* __restrict__ wlo,
    float* __restrict__ C, int n, int do_head,
    const float* __restrict__ b1, const float* __restrict__ w2,
    const float* __restrict__ b2p, const int* __restrict__ mask,
    float* __restrict__ S)
{
    extern __shared__ __align__(16) unsigned short smem[];
    unsigned short* Bhi = smem;
    unsigned short* Blo = Bhi + TILE_USH;
    unsigned short* Ahi = Blo + TILE_USH;
    unsigned short* Alo = Ahi + ACH_USH;

    const int tid = threadIdx.x;
    const int wid = tid >> 5;
    const int lane = tid & 31;
    const int r0 = blockIdx.x * 128;
    const int wr = wid * 16;

    // ---- load weight tiles into padded smem (full k=128)
    {
        const uint4* sh = (const uint4*)whi;
        const uint4* sl = (const uint4*)wlo;
#pragma unroll
        for (int p = 0; p < 8; p++) {
            int i = p * 256 + tid;
            int row = i >> 4;
            int c8 = i & 15;
            *(uint4*)(Bhi + row * TP + c8 * 8) = sh[i];
            *(uint4*)(Blo + row * TP + c8 * 8) = sl[i];
        }
    }

    // fragment addressing
    uint32_t a_row = (uint32_t)(wr + ((lane >> 3) & 1) * 8 + (lane & 7));
    uint32_t a_colb = (uint32_t)((lane >> 4) * 8) * 2;
    uint32_t ahi_base = smem_u32(Ahi) + a_row * (TPA * 2) + a_colb;
    uint32_t alo_base = smem_u32(Alo) + a_row * (TPA * 2) + a_colb;
    uint32_t b_row = (uint32_t)((lane >> 4) * 8 + (lane & 7));
    uint32_t b_col = (uint32_t)(((lane >> 3) & 1) * 8);
    uint32_t bhi_base = smem_u32(Bhi) + (b_row * TP + b_col) * 2;
    uint32_t blo_base = smem_u32(Blo) + (b_row * TP + b_col) * 2;

    float d[16][4];
#pragma unroll
    for (int i = 0; i < 16; i++)
#pragma unroll
        for (int j = 0; j < 4; j++) d[i][j] = 0.f;

#pragma unroll
    for (int kc = 0; kc < 2; kc++) {
        __syncthreads();   // previous chunk's mma done before overwrite
#pragma unroll
        for (int it = 0; it < 8; it++) {
            int idx = it * 256 + tid;
            int row = idx >> 4;
            int c4 = idx & 15;
            int grow = r0 + row;
            float4 v = make_float4(0.f, 0.f, 0.f, 0.f);
            if (grow < n)
                v = *(const float4*)(A + (size_t)grow * DD + kc * 64 + c4 * 4);

            uint2 hp, lp;
            split2_pair(v.x, v.y, hp.x, lp.x);
            split2_pair(v.z, v.w, hp.y, lp.y);
            *(uint2*)(Ahi + row * TPA + c4 * 4) = hp;
            *(uint2*)(Alo + row * TPA + c4 * 4) = lp;
        }
        __syncthreads();

#pragma unroll
        for (int ks = 0; ks < 4; ks++) {
            uint32_t koff_a = (uint32_t)(ks * 16) * 2;
            uint32_t koff_b = (uint32_t)((kc * 64 + ks * 16) * 2);
            uint32_t ahi[4], alo[4];
            ldsm_x4(ahi, ahi_base + koff_a);
            ldsm_x4(alo, alo_base + koff_a);
#pragma unroll
            for (int nt2 = 0; nt2 < 8; nt2++) {
                uint32_t noff = (uint32_t)(nt2 * 16 * TP) * 2;
                uint32_t bh[4], bl[4];
                ldsm_x4(bh, bhi_base + noff + koff_b);
                ldsm_x4(bl, blo_base + noff + koff_b);
                mma_bf16(d[2 * nt2],     ahi, bh[0], bh[1]);
                mma_bf16(d[2 * nt2],     ahi, bl[0], bl[1]);
                mma_bf16(d[2 * nt2],     alo, bh[0], bh[1]);
                mma_bf16(d[2 * nt2 + 1], ahi, bh[2], bh[3]);
                mma_bf16(d[2 * nt2 + 1], ahi, bl[2], bl[3]);
                mma_bf16(d[2 * nt2 + 1], alo, bh[2], bh[3]);
            }
        }
    }

    // ---- epilogue
    const int g = lane >> 2;
    const int t = lane & 3;
    const int row0 = r0 + wr + g;
    const int row1 = row0 + 8;
    const bool p0 = row0 < n;
    const bool p1 = row1 < n;

    if (!do_head) {
#pragma unroll
        for (int nt = 0; nt < 16; nt++) {
            int col = nt * 8 + t * 2;
            if (p0)
                *(float2*)(C + (size_t)row0 * DD + col) = make_float2(d[nt][0], d[nt][1]);
            if (p1)
                *(float2*)(C + (size_t)row1 * DD + col) = make_float2(d[nt][2], d[nt][3]);
        }
    } else {
        float s0 = 0.f, s1 = 0.f;
#pragma unroll
        for (int nt = 0; nt < 16; nt++) {
            int c = nt * 8 + t * 2;
            float bb0 = b1[c], bb1 = b1[c + 1];
            float w0 = w2[c],  w1 = w2[c + 1];
            s0 += fmaxf(d[nt][0] + bb0, 0.f) * w0 + fmaxf(d[nt][1] + bb1, 0.f) * w1;
            s1 += fmaxf(d[nt][2] + bb0, 0.f) * w0 + fmaxf(d[nt][3] + bb1, 0.f) * w1;
        }
#pragma unroll
        for (int o = 1; o < 4; o <<= 1) {
            s0 += __shfl_xor_sync(0xffffffffu, s0, o);
            s1 += __shfl_xor_sync(0xffffffffu, s1, o);
        }
        if (t == 0) {
            float b2 = b2p[0];
            if (p0) {
                float sv = s0 + b2;
                if (mask[row0] == 0) sv = -1e9f;
                S[row0] = sv;
            }
            if (p1) {
                float sv = s1 + b2;
                if (mask[row1] == 0) sv = -1e9f;
                S[row1] = sv;
            }
        }
    }
}

// ---------------------------------------------------------------------------
// gather-aggregate: one warp per node, 2-wide software-pipelined edge loop
// OUT[i] = relu?( H[i]*dinv[i]^2 + bias + sum_{e in CSR[i]} H[src_e]*en_e )
// (round-11 proven version)
// ---------------------------------------------------------------------------
__global__ __launch_bounds__(256) void k_aggregate(const float* __restrict__ H,
                                                   const int* __restrict__ offs,
                                                   const int2* __restrict__ sorted,
                                                   const float* __restrict__ dinv,
                                                   const float* __restrict__ bias,
                                                   float* __restrict__ OUT,
                                                   int do_relu)
{
    int g = blockIdx.x * blockDim.x + threadIdx.x;
    int i = g >> 5;
    int lane = g & 31;
    if (i >= NN) return;

    float di = dinv[i];
    float sn = di * di;

    float4 h = *(const float4*)(H + (size_t)i * DD + lane * 4);
    float4 b = *(const float4*)(bias + lane * 4);
    float4 acc = make_float4(fmaf(h.x, sn, b.x), fmaf(h.y, sn, b.y),
                             fmaf(h.z, sn, b.z), fmaf(h.w, sn, b.w));

    int e0 = offs[i];
    int e1 = offs[i + 1];

    int e = e0;
    for (; e + 1 < e1; e += 2) {
        int2 pa = sorted[e];
        int2 pb = sorted[e + 1];
        float4 va = *(const float4*)(H + (size_t)pa.x * DD + lane * 4);
        float4 vb = *(const float4*)(H + (size_t)pb.x * DD + lane * 4);
        float ea = __int_as_float(pa.y);
        float eb = __int_as_float(pb.y);
        acc.x = fmaf(va.x, ea, acc.x);
        acc.y = fmaf(va.y, ea, acc.y);
        acc.z = fmaf(va.z, ea, acc.z);
        acc.w = fmaf(va.w, ea, acc.w);
        acc.x = fmaf(vb.x, eb, acc.x);
        acc.y = fmaf(vb.y, eb, acc.y);
        acc.z = fmaf(vb.z, eb, acc.z);
        acc.w = fmaf(vb.w, eb, acc.w);
    }
    if (e < e1) {
        int2 p = sorted[e];
        float en = __int_as_float(p.y);
        float4 v = *(const float4*)(H + (size_t)p.x * DD + lane * 4);
        acc.x = fmaf(v.x, en, acc.x);
        acc.y = fmaf(v.y, en, acc.y);
        acc.z = fmaf(v.z, en, acc.z);
        acc.w = fmaf(v.w, en, acc.w);
    }

    if (do_relu) {
        acc.x = fmaxf(acc.x, 0.f); acc.y = fmaxf(acc.y, 0.f);
        acc.z = fmaxf(acc.z, 0.f); acc.w = fmaxf(acc.w, 0.f);
    }
    *(float4*)(OUT + (size_t)i * DD + lane * 4) = acc;
}

// ---------------------------------------------------------------------------
// per-graph segment softmax — ONE WARP per graph (batch is sorted)
// ---------------------------------------------------------------------------
__device__ __forceinline__ int lower_bound(const int* __restrict__ a, int n, int v) {
    int lo = 0, hi = n;
    while (lo < hi) {
        int mid = (lo + hi) >> 1;
        if (a[mid] < v) lo = mid + 1; else hi = mid;
    }
    return lo;
}

__global__ __launch_bounds__(256) void k_softmax_w(const float* __restrict__ S,
                                                   const int* __restrict__ batch,
                                                   float* __restrict__ out)
{
    int gw = (blockIdx.x * blockDim.x + threadIdx.x) >> 5;   // global warp = graph id
    int lane = threadIdx.x & 31;
    if (gw >= NG) return;

    int start = lower_bound(batch, NN, gw);
    int end = lower_bound(batch, NN, gw + 1);
    if (start >= end) return;

    float m = -3.4e38f;
    for (int i = start + lane; i < end; i += 32) m = fmaxf(m, S[i]);
#pragma unroll
    for (int o = 16; o > 0; o >>= 1) m = fmaxf(m, __shfl_xor_sync(0xffffffffu, m, o));

    float z = 0.f;
    for (int i = start + lane; i < end; i += 32) {
        float e = expf(S[i] - m);
        out[i] = e;
        z += e;
    }
#pragma unroll
    for (int o = 16; o > 0; o >>= 1) z += __shfl_xor_sync(0xffffffffu, z, o);

    float inv = 1.0f / z;
    for (int i = start + lane; i < end; i += 32) out[i] *= inv;
}

// ---------------------------------------------------------------------------
// launch: CSR chain forked onto a second stream, joined before first aggregate
// ---------------------------------------------------------------------------
extern "C" void kernel_launch(void* const* d_in, const int* in_sizes, int n_in,
                              void* d_out, int out_size)
{
    const float* x       = (const float*)d_in[0];
    const int*   eidx    = (const int*)d_in[1];
    const int*   batch   = (const int*)d_in[2];
    const int*   mask    = (const int*)d_in[3];
    const float* gcn_w   = (const float*)d_in[4];
    const float* gcn_b   = (const float*)d_in[5];
    const float* lin1_w  = (const float*)d_in[6];
    const float* lin1_b  = (const float*)d_in[7];
    const float* lin2_w  = (const float*)d_in[8];
    const float* lin2_b  = (const float*)d_in[9];
    float* out = (float*)d_out;

    const int* src = eidx;
    const int* dst = eidx + NE;

    float *bufA, *bufB, *dinv, *sbuf;
    int *counts, *rank, *offs, *stat;
    int2 *sorted;
    unsigned short *whi, *wlo;
    cudaGetSymbolAddress((void**)&bufA, g_bufA);
    cudaGetSymbolAddress((void**)&bufB, g_bufB);
    cudaGetSymbolAddress((void**)&dinv, g_dinv);
    cudaGetSymbolAddress((void**)&sbuf, g_s);
    cudaGetSymbolAddress((void**)&counts, g_counts);
    cudaGetSymbolAddress((void**)&rank, g_rank);
    cudaGetSymbolAddress((void**)&offs, g_offs);
    cudaGetSymbolAddress((void**)&stat, g_stat);
    cudaGetSymbolAddress((void**)&sorted, g_sorted);
    cudaGetSymbolAddress((void**)&whi, g_wbhi);
    cudaGetSymbolAddress((void**)&wlo, g_wblo);

    cudaFuncSetAttribute(k_gemm_mma, cudaFuncAttributeMaxDynamicSharedMemorySize, SMEMSZ);

    // fork a side stream for the CSR build (capturable fork-join pattern)
    cudaStream_t s2;
    cudaStreamCreateWithFlags(&s2, cudaStreamNonBlocking);
    cudaEvent_t evFork, evCSR;
    cudaEventCreateWithFlags(&evFork, cudaEventDisableTiming);
    cudaEventCreateWithFlags(&evCSR, cudaEventDisableTiming);

    cudaEventRecord(evFork, 0);
    cudaStreamWaitEvent(s2, evFork, 0);

    // CSR build on s2
    k_zero2<<<(NN + 255) / 256, 256, 0, s2>>>(counts, stat);
    k_hist_rank<<<(NE + 255) / 256, 256, 0, s2>>>(dst, counts, rank);
    k_scan_lb<<<NBLK, SCAN_BLK, 0, s2>>>(counts, stat, offs, dinv);
    k_place_rank<<<(NE + 255) / 256, 256, 0, s2>>>(src, dst, rank, offs, dinv, sorted);
    cudaEventRecord(evCSR, s2);

    const int agg_blocks = (NN * 32 + 255) / 256;

    // main stream: weight prep + layer-0 GEMM overlap with the CSR build
    k_prepw<<<4, 256>>>(gcn_w, lin1_w, whi, wlo);
    k_gemm_mma<<<GEMM_TILES, 256, SMEMSZ>>>(x, whi, wlo, bufB, NN, 0,
                                            nullptr, nullptr, nullptr, nullptr, nullptr);

    // join: aggregate needs offs/sorted/dinv
    cudaStreamWaitEvent(0, evCSR, 0);

    const float* in_ptr = nullptr;
    for (int l = 0; l < NL; l++) {
        if (l > 0) {
            k_gemm_mma<<<GEMM_TILES, 256, SMEMSZ>>>(in_ptr,
                                                    whi + (size_t)l * 16384,
                                                    wlo + (size_t)l * 16384,
                                                    bufB, NN, 0,
                                                    nullptr, nullptr, nullptr, nullptr, nullptr);
        }
        k_aggregate<<<agg_blocks, 256>>>(bufB, offs, sorted, dinv,
                                         gcn_b + (size_t)l * DD, bufA,
                                         (l < NL - 1) ? 1 : 0);
        in_ptr = bufA;
    }

    // MLP GEMM with fused head -> per-node score
    k_gemm_mma<<<GEMM_TILES, 256, SMEMSZ>>>(bufA, whi + (size_t)3 * 16384,
                                            wlo + (size_t)3 * 16384,
                                            nullptr, NN, 1,
                                            lin1_b, lin2_w, lin2_b, mask, sbuf);

    // per-graph softmax (one warp per graph)
    k_softmax_w<<<(NG * 32 + 255) / 256, 256>>>(sbuf, batch, out);

    cudaEventDestroy(evFork);
    cudaEventDestroy(evCSR);
    cudaStreamDestroy(s2);
}